// round 13
// baseline (speedup 1.0000x reference)
#include <cuda_runtime.h>

// EKVNonLinearConv: single-kernel. w-space PWL table (built in-block with fast
// intrinsics) + per-(ci)-fused sorted term lists (sorted in-block by warp 0) with
// per-(ci,warp) counted prefix, entry loop unrolled by 2 via sentinel padding.
//   f(d) = sp(min(a,20))^2 - sp(min(a-D,20))^2, a=d/0.075 ; out = ALPHA*R*scale*sum f
//   u = saturate(vg*INVR + ub), ub=(0.96-clip(th,1,8))/2.56 ; w = u*(1-2^-23)+1 in [1,2)
//   idx = top 9 mantissa bits of w ; 512 intervals, h_d = 0.005 ; kinks d=1.5 -> 492,
//   d=1.6 -> right edge of 511 (line passes through 0 there). Skip margin 0.55:
//   dropped terms contribute < 5e-7 absolute. Sentinel entries -> u=0 -> ~5e-12.

#define CIN    16
#define COUTT  64
#define HH     32
#define WW     32
#define BB     8
#define CG     2
#define NWARP  8
#define PR     2
#define NTHR   256
#define RPB    16             // NWARP*PR output rows per block
#define TILR   18             // +2 halo
#define LPC    144
#define NCG    32             // cout-pair groups
#define LSTRIDE 10            // 9 real entries + 1 sentinel

#define TABN   512
#define TD0    (-0.96f)
#define THD    0.005f                // 2.56/512
#define INVR   0.390625f             // 1/2.56 (exact dyadic)
#define SCL2   0.99999988f           // 1 - 2^-23: keeps w < 2.0 at u == 1
#define CUTC   0.41f                 // 0.96 - 0.55 (skip margin)

__device__ __forceinline__ float ekv_fast(float d) {
    // d in [-0.96, 1.62] -> a in [-12.8, 21.6]; no lower clip needed (> -50)
    const float INVD  = 13.333333333333334f;
    const float DELTA = 1.3333333333333333f;
    float a  = d * INVD;
    float a1 = fminf(a, 20.0f);
    float a2 = fminf(a - DELTA, 20.0f);
    float l1 = __logf(1.0f + __expf(a1));
    float l2 = __logf(1.0f + __expf(a2));
    return fmaf(l1, l1, -l2 * l2);
}

__global__ __launch_bounds__(NTHR)
void ekv_conv_kernel(const float* __restrict__ x,
                     const float* __restrict__ theta,
                     const float* __restrict__ scale,
                     float* __restrict__ out)
{
    __shared__ float  sx[CIN][TILR][34];     // 38.25 KB halo tile
    __shared__ float4 slist[CIN * LSTRIDE];  // 2.5 KB fused sorted lists (+sentinels)
    __shared__ float2 tab[TABN];             // 4 KB
    __shared__ float  srm[CIN][TILR];        // per-(ci,row) max
    __shared__ int    scnt[CIN][NWARP];      // per-(ci,warp) active prefix length

    const int rt = blockIdx.x;       // 0..1
    const int cg = blockIdx.y;       // 0..31
    const int b  = blockIdx.z;
    const int y0 = rt * RPB;
    const int tid = threadIdx.x;

    // ---- build w-space table in-block (2 entries/thread, fast intrinsics) ----
    for (int i = tid; i < TABN; i += NTHR) {
        float f0 = ekv_fast(TD0 + (float)i * THD);
        float f1 = ekv_fast(TD0 + (float)(i + 1) * THD);
        float a1 = (f1 - f0) * 512.0f;                // slope per unit w
        float w0 = 1.0f + (float)i * (1.0f / 512.0f);
        tab[i] = make_float2(fmaf(-a1, w0, f0), a1);
    }

    // ---- warp 0: sort this block's 32 lists (one per (ci, c)) in registers ----
    if (tid < CIN * CG) {
        const int ci = tid >> 1, c = tid & 1;
        float ub[9]; int off[9];
        const float* tp = theta + (cg * CG + c) * LPC + ci * 9;
        #pragma unroll
        for (int e = 0; e < 9; e++) {
            float th = fminf(fmaxf(tp[e], 1.0f), 8.0f);
            ub[e] = (0.96f - th) * INVR;
            int ky = e / 3, kx = e - ky * 3;
            off[e] = (ky * 34 + kx) * 4;          // byte offset in tile slab
        }
        #pragma unroll
        for (int i = 0; i < 8; i++) {             // selection sort, descending
            int m = i;
            #pragma unroll
            for (int j = i + 1; j < 9; j++) if (ub[j] > ub[m]) m = j;
            float tu = ub[i]; ub[i] = ub[m]; ub[m] = tu;
            int   to = off[i]; off[i] = off[m]; off[m] = to;
        }
        float* dst = (float*)&slist[ci * LSTRIDE];
        #pragma unroll
        for (int e = 0; e < 9; e++) {
            dst[e * 4 + c * 2 + 0] = ub[e];
            dst[e * 4 + c * 2 + 1] = __int_as_float(off[e]);
        }
        dst[9 * 4 + c * 2 + 0] = -4.0f;           // sentinel: u -> 0 -> f ~ 5e-12
        dst[9 * 4 + c * 2 + 1] = 0.0f;
    }

    // ---- load x halo tile (zero-padded) ----
    for (int i = tid; i < CIN * TILR * 34; i += NTHR) {
        int cc = i % 34;
        int r  = (i / 34) % TILR;
        int ci = i / (34 * TILR);
        int gy = y0 - 1 + r;
        int gx = cc - 1;
        float v = 0.0f;
        if (gy >= 0 && gy < HH && gx >= 0 && gx < WW)
            v = x[((b * CIN + ci) * HH + gy) * WW + gx];
        sx[ci][r][cc] = v;
    }
    __syncthreads();

    // ---- per-(ci,row) max ----
    for (int i = tid; i < CIN * TILR; i += NTHR) {
        int r  = i % TILR;
        int ci = i / TILR;
        float m = -1e30f;
        #pragma unroll
        for (int cc = 0; cc < 34; cc++) m = fmaxf(m, sx[ci][r][cc]);
        srm[ci][r] = m;
    }
    __syncthreads();

    // ---- per-(ci,warp) active prefix length over the fused list ----
    if (tid < CIN * NWARP) {
        int w = tid & 7, ci = tid >> 3;
        float m = fmaxf(fmaxf(srm[ci][2 * w], srm[ci][2 * w + 1]),
                        fmaxf(srm[ci][2 * w + 2], srm[ci][2 * w + 3]));
        float cut = (CUTC - m) * INVR;
        const float4* l = &slist[ci * LSTRIDE];
        int n = 0;
        #pragma unroll
        for (int e = 0; e < 9; e++)
            if (fmaxf(l[e].x, l[e].z) > cut) n++;   // sorted -> prefix length
        scnt[ci][w] = n;
    }
    __syncthreads();

    const int tx  = tid & 31;
    const int wid = tid >> 5;

    float accA0 = 0.0f, accB0 = 0.0f;   // cout c0,   pixel rows A/B
    float accA1 = 0.0f, accB1 = 0.0f;   // cout c0+1

#define EKV_PIX(VG, UB, ACC) do {                                    \
        float u_ = __saturatef(fmaf((VG), INVR, (UB)));              \
        float w_ = fmaf(u_, SCL2, 1.0f);                             \
        int o_ = (__float_as_int(w_) >> 11) & 0xFF8;                 \
        float2 e_ = *(const float2*)((const char*)tab + o_);         \
        (ACC) += fmaf(e_.y, w_, e_.x);                               \
    } while (0)

#define EKV_ENTRY(PE) do {                                           \
        const float* p0_ = (const float*)(base + __float_as_int((PE).y)); \
        const float* p1_ = (const float*)(base + __float_as_int((PE).w)); \
        float vA0_ = p0_[0], vB0_ = p0_[34];                         \
        float vA1_ = p1_[0], vB1_ = p1_[34];                         \
        EKV_PIX(vA0_, (PE).x, accA0);                                \
        EKV_PIX(vB0_, (PE).x, accB0);                                \
        EKV_PIX(vA1_, (PE).z, accA1);                                \
        EKV_PIX(vB1_, (PE).z, accB1);                                \
    } while (0)

    #pragma unroll 1
    for (int ci = 0; ci < CIN; ci++) {
        const int n2 = (scnt[ci][wid] + 1) & ~1;           // round up to even (<= 10)
        const char* base = (const char*)&sx[ci][wid * PR][tx];
        const float4* l = &slist[ci * LSTRIDE];
        #pragma unroll 1
        for (int e = 0; e < n2; e += 2) {
            float4 pe0 = l[e];
            float4 pe1 = l[e + 1];
            EKV_ENTRY(pe0);
            EKV_ENTRY(pe1);
        }
    }
#undef EKV_ENTRY
#undef EKV_PIX

    const float sc = scale[0] * (0.05625f * 0.1f);   // ALPHA * R * scale
    const int yA = y0 + wid * PR;
    const int co = cg * CG;
    out[((b * COUTT + co + 0) * HH + yA + 0) * WW + tx] = accA0 * sc;
    out[((b * COUTT + co + 0) * HH + yA + 1) * WW + tx] = accB0 * sc;
    out[((b * COUTT + co + 1) * HH + yA + 0) * WW + tx] = accA1 * sc;
    out[((b * COUTT + co + 1) * HH + yA + 1) * WW + tx] = accB1 * sc;
}

extern "C" void kernel_launch(void* const* d_in, const int* in_sizes, int n_in,
                              void* d_out, int out_size) {
    const float* x     = (const float*)d_in[0];
    const float* theta = (const float*)d_in[1];
    const float* scale = (const float*)d_in[2];
    float* out = (float*)d_out;
    (void)in_sizes; (void)n_in; (void)out_size;

    dim3 grid(HH / RPB, NCG, BB);   // 2 x 32 x 8 = 512 blocks
    dim3 block(NTHR);
    ekv_conv_kernel<<<grid, block>>>(x, theta, scale, out);
}

// round 17
// speedup vs baseline: 1.6804x; 1.6804x over previous
#include <cuda_runtime.h>

// EKVNonLinearConv: single kernel. w-space PWL table (built in-block, midpoints shared)
// + per-ci fused sorted term lists (spill-free rank sort, static register indexing)
// + per-(ci,warp) counted prefix hot loop (R12 structure).
//   f(d) = sp(min(a,20))^2 - sp(min(a-D,20))^2, a=d/0.075 ; out = ALPHA*R*scale*sum f
//   u = saturate(vg*INVR + ub), ub=(0.96-clip(th,1,8))/2.56 ; w = u*(1-2^-23)+1 in [1,2)
//   idx = top 9 mantissa bits of w ; 512 intervals, h_d=0.005 ; kinks d=1.5->492,
//   d=1.6 -> right edge of 511 (line passes through 0 there). Skip margin 0.55:
//   dropped terms contribute < 5e-7 absolute.

#define CIN    16
#define COUTT  64
#define HH     32
#define WW     32
#define BB     8
#define CG     2
#define NWARP  8
#define PR     2
#define NTHR   256
#define RPB    16             // NWARP*PR output rows per block
#define TILR   18             // +2 halo
#define LPC    144
#define NCG    32             // cout-pair groups

#define TABN   512
#define TD0    (-0.96f)
#define THD    0.005f                // 2.56/512
#define INVR   0.390625f             // 1/2.56 (exact dyadic)
#define SCL2   0.99999988f           // 1 - 2^-23: keeps w < 2.0 at u == 1
#define CUTC   0.41f                 // 0.96 - 0.55 (skip margin)

__device__ __forceinline__ float ekv_fast(float d) {
    // d in [-0.96, 1.625] -> a in [-12.8, 21.7]; lower clip (-50) never binds
    const float INVD  = 13.333333333333334f;
    const float DELTA = 1.3333333333333333f;
    float a  = d * INVD;
    float a1 = fminf(a, 20.0f);
    float a2 = fminf(a - DELTA, 20.0f);
    float l1 = __logf(1.0f + __expf(a1));
    float l2 = __logf(1.0f + __expf(a2));
    return fmaf(l1, l1, -l2 * l2);
}

__global__ __launch_bounds__(NTHR)
void ekv_conv_kernel(const float* __restrict__ x,
                     const float* __restrict__ theta,
                     const float* __restrict__ scale,
                     float* __restrict__ out)
{
    __shared__ float  sx[CIN][TILR][34];   // 38.25 KB halo tile
    __shared__ float4 slist[CIN * 9];      // 2.25 KB fused sorted lists
    __shared__ float2 tab[TABN];           // 4 KB
    __shared__ float  stv[TABN + 1];       // 2 KB table node values
    __shared__ float  srm[CIN][TILR];      // per-(ci,row) max
    __shared__ int    scnt[CIN][NWARP];    // per-(ci,warp) active prefix length

    const int rt = blockIdx.x;       // 0..1
    const int cg = blockIdx.y;       // 0..31
    const int b  = blockIdx.z;
    const int y0 = rt * RPB;
    const int tid = threadIdx.x;

    // ---- phase 1: table node values + tile load + rank-sorted lists ----
    for (int i = tid; i <= TABN; i += NTHR)
        stv[i] = ekv_fast(TD0 + (float)i * THD);

    if (tid < CIN * CG) {              // one thread per (ci, c): rank sort, no spills
        const int ci = tid >> 1, c = tid & 1;
        const float* tp = theta + (cg * CG + c) * LPC + ci * 9;
        float ub[9];
        #pragma unroll
        for (int e = 0; e < 9; e++) {
            float th = fminf(fmaxf(tp[e], 1.0f), 8.0f);
            ub[e] = (0.96f - th) * INVR;
        }
        float* dst = (float*)&slist[ci * 9];
        #pragma unroll
        for (int e = 0; e < 9; e++) {   // rank = #greater (+ index tie-break)
            int rank = 0;
            #pragma unroll
            for (int j = 0; j < 9; j++)
                rank += (ub[j] > ub[e]) || (ub[j] == ub[e] && j < e);
            int ky = e / 3, kx = e - ky * 3;
            dst[rank * 4 + c * 2 + 0] = ub[e];
            dst[rank * 4 + c * 2 + 1] = __int_as_float((ky * 34 + kx) * 4);
        }
    }

    for (int i = tid; i < CIN * TILR * 34; i += NTHR) {
        int cc = i % 34;
        int r  = (i / 34) % TILR;
        int ci = i / (34 * TILR);
        int gy = y0 - 1 + r;
        int gx = cc - 1;
        float v = 0.0f;
        if (gy >= 0 && gy < HH && gx >= 0 && gx < WW)
            v = x[((b * CIN + ci) * HH + gy) * WW + gx];
        sx[ci][r][cc] = v;
    }
    __syncthreads();

    // ---- phase 2: table slopes + per-(ci,row) max ----
    for (int i = tid; i < TABN; i += NTHR) {
        float f0 = stv[i], f1 = stv[i + 1];
        float a1 = (f1 - f0) * 512.0f;                // slope per unit w
        float w0 = 1.0f + (float)i * (1.0f / 512.0f);
        tab[i] = make_float2(fmaf(-a1, w0, f0), a1);
    }
    for (int i = tid; i < CIN * TILR; i += NTHR) {
        int r  = i % TILR;
        int ci = i / TILR;
        float m = -1e30f;
        #pragma unroll
        for (int cc = 0; cc < 34; cc++) m = fmaxf(m, sx[ci][r][cc]);
        srm[ci][r] = m;
    }
    __syncthreads();

    // ---- phase 3: per-(ci,warp) active prefix length ----
    if (tid < CIN * NWARP) {
        int w = tid & 7, ci = tid >> 3;
        float m = fmaxf(fmaxf(srm[ci][2 * w], srm[ci][2 * w + 1]),
                        fmaxf(srm[ci][2 * w + 2], srm[ci][2 * w + 3]));
        float cut = (CUTC - m) * INVR;
        const float4* l = &slist[ci * 9];
        int n = 0;
        #pragma unroll
        for (int e = 0; e < 9; e++)
            if (fmaxf(l[e].x, l[e].z) > cut) n++;   // sorted -> prefix length
        scnt[ci][w] = n;
    }
    __syncthreads();

    const int tx  = tid & 31;
    const int wid = tid >> 5;

    float accA0 = 0.0f, accB0 = 0.0f;   // cout c0,   pixel rows A/B
    float accA1 = 0.0f, accB1 = 0.0f;   // cout c0+1

#define EKV_PIX(VG, UB, ACC) do {                                    \
        float u_ = __saturatef(fmaf((VG), INVR, (UB)));              \
        float w_ = fmaf(u_, SCL2, 1.0f);                             \
        int o_ = (__float_as_int(w_) >> 11) & 0xFF8;                 \
        float2 e_ = *(const float2*)((const char*)tab + o_);         \
        (ACC) += fmaf(e_.y, w_, e_.x);                               \
    } while (0)

    #pragma unroll 1
    for (int ci = 0; ci < CIN; ci++) {
        const int n = scnt[ci][wid];                       // warp-uniform
        const char* base = (const char*)&sx[ci][wid * PR][tx];
        const float4* l = &slist[ci * 9];
        #pragma unroll 1
        for (int e = 0; e < n; e++) {
            float4 pe = l[e];                              // 1 LDS.128, broadcast
            const float* p0 = (const float*)(base + __float_as_int(pe.y));
            const float* p1 = (const float*)(base + __float_as_int(pe.w));
            float vA0 = p0[0], vB0 = p0[34];
            float vA1 = p1[0], vB1 = p1[34];
            EKV_PIX(vA0, pe.x, accA0);                     // 4 independent chains
            EKV_PIX(vB0, pe.x, accB0);
            EKV_PIX(vA1, pe.z, accA1);
            EKV_PIX(vB1, pe.z, accB1);
        }
    }
#undef EKV_PIX

    const float sc = scale[0] * (0.05625f * 0.1f);   // ALPHA * R * scale
    const int yA = y0 + wid * PR;
    const int co = cg * CG;
    out[((b * COUTT + co + 0) * HH + yA + 0) * WW + tx] = accA0 * sc;
    out[((b * COUTT + co + 0) * HH + yA + 1) * WW + tx] = accB0 * sc;
    out[((b * COUTT + co + 1) * HH + yA + 0) * WW + tx] = accA1 * sc;
    out[((b * COUTT + co + 1) * HH + yA + 1) * WW + tx] = accB1 * sc;
}

extern "C" void kernel_launch(void* const* d_in, const int* in_sizes, int n_in,
                              void* d_out, int out_size) {
    const float* x     = (const float*)d_in[0];
    const float* theta = (const float*)d_in[1];
    const float* scale = (const float*)d_in[2];
    float* out = (float*)d_out;
    (void)in_sizes; (void)n_in; (void)out_size;

    dim3 grid(HH / RPB, NCG, BB);   // 2 x 32 x 8 = 512 blocks
    dim3 block(NTHR);
    ekv_conv_kernel<<<grid, block>>>(x, theta, scale, out);
}